// round 16
// baseline (speedup 1.0000x reference)
#include <cuda_runtime.h>
#include <cuda_bf16.h>
#include <cuda_fp16.h>
#include <cstdint>
#include <cstddef>

#define BB 16
#define LL 4096
#define DD 64
#define TQ 128
#define TK 128
#define NQT (LL / TQ)          // 32
// Q prescale: 1/(T+eps) * log2(e), so scores are base-2 exponents
#define QSCALE (1.44269504088896f / (8.0f + 1e-6f))

// ---------------- global scratch (no cudaMalloc allowed) --------------------
__device__ __align__(16) __half g_Qh[(size_t)BB * LL * DD];    // Q*QSCALE, fp16
__device__ __align__(16) __half g_Kh[(size_t)BB * LL * DD];    // K, fp16
__device__ __align__(16) __half g_Vh[(size_t)BB * LL * DD];    // V, fp16 [b][key][d]
__device__ __align__(16) __half g_pattn[(size_t)BB * LL * LL]; // unnormalized p, fp16

// ---------------- helpers ---------------------------------------------------
__device__ __forceinline__ uint32_t smem_u32(const void* p) {
    uint32_t a;
    asm("{ .reg .u64 t; cvta.to.shared.u64 t, %1; cvt.u32.u64 %0, t; }" : "=r"(a) : "l"(p));
    return a;
}

#define SW(o) ((o) ^ (((o) >> 3) & 0x70u))   // SW128 swizzle for 128B rows

#define CP_ASYNC16(sm, gm) \
    asm volatile("cp.async.cg.shared.global [%0], [%1], 16;" :: "r"(sm), "l"(gm) : "memory")
#define CP_COMMIT() asm volatile("cp.async.commit_group;" ::: "memory")
#define CP_WAIT0()  asm volatile("cp.async.wait_group 0;" ::: "memory")

__device__ __forceinline__ void ldm_x4(uint32_t* r, uint32_t addr) {
    asm volatile("ldmatrix.sync.aligned.m8n8.x4.shared.b16 {%0,%1,%2,%3}, [%4];"
                 : "=r"(r[0]), "=r"(r[1]), "=r"(r[2]), "=r"(r[3]) : "r"(addr));
}
__device__ __forceinline__ void ldm_x4t(uint32_t* r, uint32_t addr) {
    asm volatile("ldmatrix.sync.aligned.m8n8.x4.trans.shared.b16 {%0,%1,%2,%3}, [%4];"
                 : "=r"(r[0]), "=r"(r[1]), "=r"(r[2]), "=r"(r[3]) : "r"(addr));
}
// fp16 x fp16 -> fp32 accum
__device__ __forceinline__ void mma_h(float* c, const uint32_t* a, const uint32_t* b) {
    asm volatile("mma.sync.aligned.m16n8k16.row.col.f32.f16.f16.f32 "
                 "{%0,%1,%2,%3}, {%4,%5,%6,%7}, {%8,%9}, {%0,%1,%2,%3};"
                 : "+f"(c[0]), "+f"(c[1]), "+f"(c[2]), "+f"(c[3])
                 : "r"(a[0]), "r"(a[1]), "r"(a[2]), "r"(a[3]), "r"(b[0]), "r"(b[1]));
}

// pack two floats as f16x2 (a -> low half, b -> high half), round-to-nearest
__device__ __forceinline__ uint32_t cvt_h2(float a, float b) {
    uint32_t r;
    asm("cvt.rn.f16x2.f32 %0, %1, %2;" : "=r"(r) : "f"(b), "f"(a));
    return r;
}
// 2^x, approx (scores are pre-scaled by log2(e))
__device__ __forceinline__ float ex2(float x) {
    float r;
    asm("ex2.approx.f32 %0, %1;" : "=f"(r) : "f"(x));
    return r;
}

// ---------------- prologue: Q(prescaled)/K/V -> fp16 ------------------------
__global__ __launch_bounds__(256) void convert_h(
    const float* __restrict__ q, const float* __restrict__ k,
    const float* __restrict__ v)
{
    const size_t NU = (size_t)BB * LL * DD / 8;
    size_t u = (size_t)blockIdx.x * 256 + threadIdx.x;
    const float* src; __half* dst; float sc;
    if (u < NU)          { src = q; dst = g_Qh; sc = QSCALE; }
    else if (u < 2 * NU) { u -= NU;     src = k; dst = g_Kh; sc = 1.0f; }
    else                 { u -= 2 * NU; src = v; dst = g_Vh; sc = 1.0f; }
    size_t e0 = u * 8;
    float4 a = *(const float4*)(src + e0);
    float4 c = *(const float4*)(src + e0 + 4);
    uint4 o;
    o.x = cvt_h2(a.x * sc, a.y * sc);
    o.y = cvt_h2(a.z * sc, a.w * sc);
    o.z = cvt_h2(c.x * sc, c.y * sc);
    o.w = cvt_h2(c.z * sc, c.w * sc);
    *(uint4*)(dst + e0) = o;
}

// ---------------- smem layout (bytes) ---------------------------------------
// buf(i) at i*32768: [K 16K][V 16K]; Q at 65536
#define OFF_K 0u
#define OFF_V 16384u
#define OFF_Q 65536u
#define SMEM_TOTAL 81920

__device__ __forceinline__ void issue_kv(uint32_t sb, uint32_t buf, int b, int kt, int tid) {
    const size_t koff = ((size_t)b * LL + kt * TK) * DD;
    #pragma unroll
    for (int e = 0; e < 4; e++) {
        int u = e * 256 + tid;
        int r = u >> 3, du = u & 7;
        uint32_t so = SW((uint32_t)(r * 128 + du * 16));
        size_t go = koff + (size_t)r * DD + du * 8;
        CP_ASYNC16(sb + buf + OFF_K + so, g_Kh + go);
        CP_ASYNC16(sb + buf + OFF_V + so, g_Vh + go);
    }
}

// ---------------- pass1: fused flash attention + normalized attn write ------
__global__ __launch_bounds__(256, 1) void attn_pass1(
    const unsigned char* __restrict__ mask, float* __restrict__ out,
    float* __restrict__ attn)
{
    extern __shared__ char smem[];
    const uint32_t sb = smem_u32(smem);
    const int tid = threadIdx.x;
    const int w = tid >> 5, l = tid & 31;

    // interleave long/short q-tiles so every wave mixes tensor- and DRAM-bound CTAs
    const int bx = (int)blockIdx.x;
    const int qt = (bx & 1) ? (bx >> 1) : (NQT - 1 - (bx >> 1));
    const int b = blockIdx.y;
    const int qbase = qt * TQ;

    // issue Q + KV(0)
    {
        const size_t qoff = ((size_t)b * LL + qbase) * DD;
        #pragma unroll
        for (int e = 0; e < 4; e++) {
            int u = e * 256 + tid;
            int r = u >> 3, du = u & 7;
            uint32_t so = SW((uint32_t)(r * 128 + du * 16));
            CP_ASYNC16(sb + OFF_Q + so, g_Qh + qoff + (size_t)r * DD + du * 8);
        }
        issue_kv(sb, 0, b, 0, tid);
        CP_COMMIT();
        CP_WAIT0();
        __syncthreads();
    }

    // Q A-fragments (4 k16-chunks)
    uint32_t aq[4][4];
    {
        uint32_t rowoff = (uint32_t)((w * 16 + (l & 15)) * 128 + ((l >> 4) & 1) * 16);
        #pragma unroll
        for (int c = 0; c < 4; c++)
            ldm_x4(aq[c], sb + OFF_Q + SW(rowoff + c * 32));
    }

    const int r0 = w * 16 + (l >> 2);       // local q-row (and r0+8)
    const int qi0 = qbase + r0, qi1 = qi0 + 8;
    const bool m0 = mask[(size_t)b * LL + qi0] != 0;
    const bool m1 = mask[(size_t)b * LL + qi1] != 0;
    float la0 = 0.f, la1 = 0.f;
    float oc[8][4];
    #pragma unroll
    for (int t = 0; t < 8; t++)
        #pragma unroll
        for (int e = 0; e < 4; e++) oc[t][e] = 0.f;

    for (int kt = 0; kt <= qt; kt++) {
        const uint32_t buf = (uint32_t)(kt & 1) * 32768u;
        if (kt < qt) { issue_kv(sb, (uint32_t)((kt + 1) & 1) * 32768u, b, kt + 1, tid); CP_COMMIT(); }

        // ---- QK: S[16 x 128] in C-frags sc[16][4] ----
        float sc[16][4];
        #pragma unroll
        for (int t = 0; t < 16; t++)
            #pragma unroll
            for (int e = 0; e < 4; e++) sc[t][e] = 0.f;

        #pragma unroll
        for (int t = 0; t < 16; t++) {
            #pragma unroll
            for (int cp = 0; cp < 2; cp++) {
                uint32_t off = (uint32_t)((t * 8 + (l & 7)) * 128 + cp * 64 + ((l >> 3) & 3) * 16);
                uint32_t bk[4];
                ldm_x4(bk, sb + buf + OFF_K + SW(off));
                mma_h(sc[t], aq[2 * cp], bk);
                mma_h(sc[t], aq[2 * cp + 1], bk + 2);
            }
        }

        // ---- exp2 + mask + store fp16 p + keep packed P frags ----
        const int kbase = kt * TK;
        __half* pr0 = g_pattn + ((size_t)b * LL + qi0) * LL + kbase + 2 * (l & 3);
        __half* pr1 = g_pattn + ((size_t)b * LL + qi1) * LL + kbase + 2 * (l & 3);
        uint32_t u0[16], u1[16];            // packed p: rows (r0, r0+8) per n8 tile
        #pragma unroll
        for (int t = 0; t < 16; t++) {
            int key0 = kbase + t * 8 + 2 * (l & 3);
            float p0 = (!m0 && key0     <= qi0) ? ex2(sc[t][0]) : 0.f;
            float p1 = (!m0 && key0 + 1 <= qi0) ? ex2(sc[t][1]) : 0.f;
            float p2 = (!m1 && key0     <= qi1) ? ex2(sc[t][2]) : 0.f;
            float p3 = (!m1 && key0 + 1 <= qi1) ? ex2(sc[t][3]) : 0.f;
            u0[t] = cvt_h2(p0, p1);
            u1[t] = cvt_h2(p2, p3);
            *(uint32_t*)(pr0 + t * 8) = u0[t];
            *(uint32_t*)(pr1 + t * 8) = u1[t];
            la0 += p0 + p1;
            la1 += p2 + p3;
        }

        // ---- PV: O += P * V (P frags = stored fp16 bits, exactly) ----
        #pragma unroll
        for (int c = 0; c < 8; c++) {
            uint32_t aP[4] = {u0[2 * c], u1[2 * c], u0[2 * c + 1], u1[2 * c + 1]};
            #pragma unroll
            for (int dp = 0; dp < 4; dp++) {
                uint32_t voff = (uint32_t)((c * 16 + (l & 15)) * 128 + dp * 32 + ((l >> 4) & 1) * 16);
                uint32_t bv[4];
                ldm_x4t(bv, sb + buf + OFF_V + SW(voff));
                mma_h(oc[2 * dp], aP, bv);
                mma_h(oc[2 * dp + 1], aP, bv + 2);
            }
        }

        if (kt < qt) { CP_WAIT0(); __syncthreads(); }
    }

    // ---- row sums, O epilogue ----
    la0 += __shfl_xor_sync(0xffffffffu, la0, 1);
    la0 += __shfl_xor_sync(0xffffffffu, la0, 2);
    la1 += __shfl_xor_sync(0xffffffffu, la1, 1);
    la1 += __shfl_xor_sync(0xffffffffu, la1, 2);
    const float inv0 = (la0 > 0.f) ? (1.f / la0) : 0.f;
    const float inv1 = (la1 > 0.f) ? (1.f / la1) : 0.f;
    {
        float* orow0 = out + ((size_t)b * LL + qi0) * DD + 2 * (l & 3);
        float* orow1 = out + ((size_t)b * LL + qi1) * DD + 2 * (l & 3);
        #pragma unroll
        for (int t = 0; t < 8; t++) {
            *(float2*)(orow0 + t * 8) = make_float2(oc[t][0] * inv0, oc[t][1] * inv0);
            *(float2*)(orow1 + t * 8) = make_float2(oc[t][2] * inv1, oc[t][3] * inv1);
        }
    }

    // ---- fused pass2: normalize this CTA's 128 attn rows, fill tail --------
    __syncthreads();                        // all warps done with smem K/V
    float* sinv = (float*)smem;             // reuse K buffer for per-row inv
    if ((l & 3) == 0) {
        sinv[r0] = inv0;
        sinv[r0 + 8] = inv1;
    }
    __syncthreads();

    const int limit = (qt + 1) * TK;
    const float uni = 1.0f / (float)LL;
    float* abase = attn + ((size_t)b * LL + qbase) * LL;
    const __half* pbase = g_pattn + ((size_t)b * LL + qbase) * LL;
    const unsigned char* mrow = mask + (size_t)b * LL + qbase;
    const float4 zf = make_float4(0.f, 0.f, 0.f, 0.f);
    const float4 uf = make_float4(uni, uni, uni, uni);

    for (int idx = tid * 4; idx < TQ * LL; idx += 256 * 4) {
        int r = idx >> 12;                  // row 0..127
        int c = idx & (LL - 1);
        float4 wv;
        if (mrow[r]) {
            wv = uf;
        } else if (c < limit) {
            uint2 rr = *(const uint2*)(pbase + (size_t)r * LL + c);
            float inv = sinv[r];
            float2 f0 = __half22float2(*reinterpret_cast<__half2*>(&rr.x));
            float2 f1 = __half22float2(*reinterpret_cast<__half2*>(&rr.y));
            wv = make_float4(f0.x * inv, f0.y * inv, f1.x * inv, f1.y * inv);
        } else {
            wv = zf;
        }
        *(float4*)(abase + (size_t)r * LL + c) = wv;
    }
}

// ---------------- pass3: masked rows -> uniform mean of V -------------------
__global__ __launch_bounds__(64) void attn_pass3(
    const unsigned char* __restrict__ mask,
    const float* __restrict__ v, float* __restrict__ out)
{
    const int row = blockIdx.x * 64 + threadIdx.x;   // b*L + i
    const bool m = mask[row] != 0;
    if (!__syncthreads_or(m)) return;                // fast path: no masked rows
    if (!m) return;
    const int b = row >> 12;
    const float* vb = v + (size_t)b * LL * DD;
    for (int d = 0; d < DD; d++) {
        float s = 0.f;
        for (int kk = 0; kk < LL; kk++) s += vb[(size_t)kk * DD + d];
        out[(size_t)row * DD + d] = s * (1.0f / (float)LL);
    }
}

extern "C" void kernel_launch(void* const* d_in, const int* in_sizes, int n_in,
                              void* d_out, int out_size)
{
    (void)in_sizes; (void)n_in; (void)out_size;
    const float* q = (const float*)d_in[0];
    const float* k = (const float*)d_in[1];
    const float* v = (const float*)d_in[2];
    const unsigned char* mask = (const unsigned char*)d_in[3];

    float* out = (float*)d_out;
    float* attn = out + (size_t)BB * LL * DD;

    cudaFuncSetAttribute(attn_pass1, cudaFuncAttributeMaxDynamicSharedMemorySize, SMEM_TOTAL);

    const int NCONV = (int)(3 * (size_t)BB * LL * DD / 8 / 256);  // 6144 blocks
    convert_h<<<NCONV, 256>>>(q, k, v);
    attn_pass1<<<dim3(NQT, BB), 256, SMEM_TOTAL>>>(mask, out, attn);
    attn_pass3<<<BB * LL / 64, 64>>>(mask, v, out);
}

// round 17
// speedup vs baseline: 2.1434x; 2.1434x over previous
#include <cuda_runtime.h>
#include <cuda_bf16.h>
#include <cuda_fp16.h>
#include <cstdint>
#include <cstddef>

#define BB 16
#define LL 4096
#define DD 64
#define TQ 128
#define TK 128
#define NQT (LL / TQ)          // 32
// Q prescale: 1/(T+eps) * log2(e) -> scores are base-2 exponents for ex2
#define QSCALE (1.44269504088896f / (8.0f + 1e-6f))

// ---------------- global scratch (no cudaMalloc allowed) --------------------
__device__ __align__(16) __half g_Qh[(size_t)BB * LL * DD];    // Q*QSCALE, fp16
__device__ __align__(16) __half g_Kh[(size_t)BB * LL * DD];    // K, fp16
__device__ __align__(16) __half g_Vh[(size_t)BB * LL * DD];    // V, fp16 [b][key][d]
__device__ __align__(16) __half g_pattn[(size_t)BB * LL * LL]; // unnormalized p, fp16
__device__ float g_lsum[BB * LL];

// ---------------- helpers ---------------------------------------------------
__device__ __forceinline__ uint32_t smem_u32(const void* p) {
    uint32_t a;
    asm("{ .reg .u64 t; cvta.to.shared.u64 t, %1; cvt.u32.u64 %0, t; }" : "=r"(a) : "l"(p));
    return a;
}

#define SW(o) ((o) ^ (((o) >> 3) & 0x70u))   // SW128 swizzle for 128B rows

#define CP_ASYNC16(sm, gm) \
    asm volatile("cp.async.cg.shared.global [%0], [%1], 16;" :: "r"(sm), "l"(gm) : "memory")
#define CP_COMMIT() asm volatile("cp.async.commit_group;" ::: "memory")
#define CP_WAIT0()  asm volatile("cp.async.wait_group 0;" ::: "memory")

__device__ __forceinline__ void ldm_x4(uint32_t* r, uint32_t addr) {
    asm volatile("ldmatrix.sync.aligned.m8n8.x4.shared.b16 {%0,%1,%2,%3}, [%4];"
                 : "=r"(r[0]), "=r"(r[1]), "=r"(r[2]), "=r"(r[3]) : "r"(addr));
}
__device__ __forceinline__ void ldm_x4t(uint32_t* r, uint32_t addr) {
    asm volatile("ldmatrix.sync.aligned.m8n8.x4.trans.shared.b16 {%0,%1,%2,%3}, [%4];"
                 : "=r"(r[0]), "=r"(r[1]), "=r"(r[2]), "=r"(r[3]) : "r"(addr));
}
// fp16 x fp16 -> fp32 accum
__device__ __forceinline__ void mma_h(float* c, const uint32_t* a, const uint32_t* b) {
    asm volatile("mma.sync.aligned.m16n8k16.row.col.f32.f16.f16.f32 "
                 "{%0,%1,%2,%3}, {%4,%5,%6,%7}, {%8,%9}, {%0,%1,%2,%3};"
                 : "+f"(c[0]), "+f"(c[1]), "+f"(c[2]), "+f"(c[3])
                 : "r"(a[0]), "r"(a[1]), "r"(a[2]), "r"(a[3]), "r"(b[0]), "r"(b[1]));
}

// pack two floats as f16x2 (a -> low half, b -> high half), round-to-nearest
__device__ __forceinline__ uint32_t cvt_h2(float a, float b) {
    uint32_t r;
    asm("cvt.rn.f16x2.f32 %0, %1, %2;" : "=r"(r) : "f"(b), "f"(a));
    return r;
}
// 2^x, approx (scores are pre-scaled by log2(e))
__device__ __forceinline__ float ex2(float x) {
    float r;
    asm("ex2.approx.f32 %0, %1;" : "=f"(r) : "f"(x));
    return r;
}

// ---------------- prologue: Q(prescaled)/K/V -> fp16 ------------------------
__global__ __launch_bounds__(256) void convert_h(
    const float* __restrict__ q, const float* __restrict__ k,
    const float* __restrict__ v)
{
    const size_t NU = (size_t)BB * LL * DD / 8;
    size_t u = (size_t)blockIdx.x * 256 + threadIdx.x;
    const float* src; __half* dst; float sc;
    if (u < NU)          { src = q; dst = g_Qh; sc = QSCALE; }
    else if (u < 2 * NU) { u -= NU;     src = k; dst = g_Kh; sc = 1.0f; }
    else                 { u -= 2 * NU; src = v; dst = g_Vh; sc = 1.0f; }
    size_t e0 = u * 8;
    float4 a = *(const float4*)(src + e0);
    float4 c = *(const float4*)(src + e0 + 4);
    uint4 o;
    o.x = cvt_h2(a.x * sc, a.y * sc);
    o.y = cvt_h2(a.z * sc, a.w * sc);
    o.z = cvt_h2(c.x * sc, c.y * sc);
    o.w = cvt_h2(c.z * sc, c.w * sc);
    *(uint4*)(dst + e0) = o;
}

// ---------------- smem layout (bytes) ---------------------------------------
// buf(i) at i*32768: [K 16K][V 16K]; Q at 65536
#define OFF_K 0u
#define OFF_V 16384u
#define OFF_Q 65536u
#define SMEM_TOTAL 81920

__device__ __forceinline__ void issue_kv(uint32_t sb, uint32_t buf, int b, int kt, int tid) {
    const size_t koff = ((size_t)b * LL + kt * TK) * DD;
    #pragma unroll
    for (int e = 0; e < 4; e++) {
        int u = e * 256 + tid;
        int r = u >> 3, du = u & 7;
        uint32_t so = SW((uint32_t)(r * 128 + du * 16));
        size_t go = koff + (size_t)r * DD + du * 8;
        CP_ASYNC16(sb + buf + OFF_K + so, g_Kh + go);
        CP_ASYNC16(sb + buf + OFF_V + so, g_Vh + go);
    }
}

// ---------------- pass1: flash-style causal attention, fp16 HMMA ------------
// Per-chunk restructure (QK -> exp -> PV per 16 keys) keeps ~100 live regs so
// 2 CTAs/SM fit; one CTA's MMAs hide the other's cp.async/exp bubbles.
__global__ __launch_bounds__(256, 2) void attn_pass1(
    const unsigned char* __restrict__ mask, float* __restrict__ out)
{
    extern __shared__ char smem[];
    const uint32_t sb = smem_u32(smem);
    const int tid = threadIdx.x;
    const int w = tid >> 5, l = tid & 31;

    const int qt = (NQT - 1) - (int)blockIdx.x;   // long tiles first
    const int b = blockIdx.y;
    const int qbase = qt * TQ;

    // issue Q + KV(0)
    {
        const size_t qoff = ((size_t)b * LL + qbase) * DD;
        #pragma unroll
        for (int e = 0; e < 4; e++) {
            int u = e * 256 + tid;
            int r = u >> 3, du = u & 7;
            uint32_t so = SW((uint32_t)(r * 128 + du * 16));
            CP_ASYNC16(sb + OFF_Q + so, g_Qh + qoff + (size_t)r * DD + du * 8);
        }
        issue_kv(sb, 0, b, 0, tid);
        CP_COMMIT();
        CP_WAIT0();
        __syncthreads();
    }

    // Q A-fragments (4 k16-chunks)
    uint32_t aq[4][4];
    {
        uint32_t rowoff = (uint32_t)((w * 16 + (l & 15)) * 128 + ((l >> 4) & 1) * 16);
        #pragma unroll
        for (int c = 0; c < 4; c++)
            ldm_x4(aq[c], sb + OFF_Q + SW(rowoff + c * 32));
    }

    const int r0 = w * 16 + (l >> 2);       // local q-row (and r0+8)
    const int qi0 = qbase + r0, qi1 = qi0 + 8;
    const bool m0 = mask[(size_t)b * LL + qi0] != 0;
    const bool m1 = mask[(size_t)b * LL + qi1] != 0;
    float la0 = 0.f, la1 = 0.f;
    float oc[8][4];
    #pragma unroll
    for (int t = 0; t < 8; t++)
        #pragma unroll
        for (int e = 0; e < 4; e++) oc[t][e] = 0.f;

    for (int kt = 0; kt <= qt; kt++) {
        const uint32_t buf = (uint32_t)(kt & 1) * 32768u;
        if (kt < qt) { issue_kv(sb, (uint32_t)((kt + 1) & 1) * 32768u, b, kt + 1, tid); CP_COMMIT(); }

        const int kbase = kt * TK;
        __half* pr0 = g_pattn + ((size_t)b * LL + qi0) * LL + kbase + 2 * (l & 3);
        __half* pr1 = g_pattn + ((size_t)b * LL + qi1) * LL + kbase + 2 * (l & 3);

        #pragma unroll
        for (int c = 0; c < 8; c++) {       // 16-key chunk = n8 tiles t0, t0+1
            const int t0 = 2 * c;

            // ---- QK for this chunk: sc[2][4] ----
            float sc[2][4];
            #pragma unroll
            for (int tt = 0; tt < 2; tt++) {
                sc[tt][0] = sc[tt][1] = sc[tt][2] = sc[tt][3] = 0.f;
                #pragma unroll
                for (int cp = 0; cp < 2; cp++) {
                    uint32_t off = (uint32_t)(((t0 + tt) * 8 + (l & 7)) * 128 +
                                              cp * 64 + ((l >> 3) & 3) * 16);
                    uint32_t bk[4];
                    ldm_x4(bk, sb + buf + OFF_K + SW(off));
                    mma_h(sc[tt], aq[2 * cp], bk);
                    mma_h(sc[tt], aq[2 * cp + 1], bk + 2);
                }
            }

            // ---- exp2 + mask + store fp16 p ----
            uint32_t u0[2], u1[2];
            #pragma unroll
            for (int tt = 0; tt < 2; tt++) {
                int key0 = kbase + (t0 + tt) * 8 + 2 * (l & 3);
                float p0 = (!m0 && key0     <= qi0) ? ex2(sc[tt][0]) : 0.f;
                float p1 = (!m0 && key0 + 1 <= qi0) ? ex2(sc[tt][1]) : 0.f;
                float p2 = (!m1 && key0     <= qi1) ? ex2(sc[tt][2]) : 0.f;
                float p3 = (!m1 && key0 + 1 <= qi1) ? ex2(sc[tt][3]) : 0.f;
                u0[tt] = cvt_h2(p0, p1);
                u1[tt] = cvt_h2(p2, p3);
                *(uint32_t*)(pr0 + (t0 + tt) * 8) = u0[tt];
                *(uint32_t*)(pr1 + (t0 + tt) * 8) = u1[tt];
                la0 += p0 + p1;
                la1 += p2 + p3;
            }

            // ---- PV for this chunk (P frags = stored fp16 bits) ----
            uint32_t aP[4] = {u0[0], u1[0], u0[1], u1[1]};
            #pragma unroll
            for (int dp = 0; dp < 4; dp++) {
                uint32_t voff = (uint32_t)((c * 16 + (l & 15)) * 128 + dp * 32 + ((l >> 4) & 1) * 16);
                uint32_t bv[4];
                ldm_x4t(bv, sb + buf + OFF_V + SW(voff));
                mma_h(oc[2 * dp], aP, bv);
                mma_h(oc[2 * dp + 1], aP, bv + 2);
            }
        }

        if (kt < qt) { CP_WAIT0(); __syncthreads(); }
    }

    // ---- row sums, O epilogue ----
    la0 += __shfl_xor_sync(0xffffffffu, la0, 1);
    la0 += __shfl_xor_sync(0xffffffffu, la0, 2);
    la1 += __shfl_xor_sync(0xffffffffu, la1, 1);
    la1 += __shfl_xor_sync(0xffffffffu, la1, 2);
    if ((l & 3) == 0) {
        g_lsum[(size_t)b * LL + qi0] = la0;
        g_lsum[(size_t)b * LL + qi1] = la1;
    }
    const float inv0 = (la0 > 0.f) ? (1.f / la0) : 0.f;
    const float inv1 = (la1 > 0.f) ? (1.f / la1) : 0.f;
    float* orow0 = out + ((size_t)b * LL + qi0) * DD + 2 * (l & 3);
    float* orow1 = out + ((size_t)b * LL + qi1) * DD + 2 * (l & 3);
    #pragma unroll
    for (int t = 0; t < 8; t++) {
        *(float2*)(orow0 + t * 8) = make_float2(oc[t][0] * inv0, oc[t][1] * inv0);
        *(float2*)(orow1 + t * 8) = make_float2(oc[t][2] * inv1, oc[t][3] * inv1);
    }
}

// ---------------- pass2: fp16 p -> normalized fp32 attn, zero tail ----------
__global__ __launch_bounds__(256) void attn_pass2(
    const unsigned char* __restrict__ mask, float* __restrict__ attn)
{
    const int row = blockIdx.x;            // b*L + i
    const int i = row & (LL - 1);
    const bool m = mask[row] != 0;
    const float lsum = g_lsum[row];
    const float inv = (lsum > 0.f) ? (1.f / lsum) : 0.f;
    const int limit = ((i >> 7) + 1) << 7;  // cols written by pass 1 (128-tiles)
    const __half* sp = g_pattn + (size_t)row * LL;
    float* ap = attn + (size_t)row * LL;
    const float uni = 1.0f / (float)LL;
    const float4 zf = make_float4(0.f, 0.f, 0.f, 0.f);
    const float4 uf = make_float4(uni, uni, uni, uni);

    for (int j = threadIdx.x * 4; j < LL; j += 256 * 4) {
        float4 wv;
        if (m) {
            wv = uf;
        } else if (j < limit) {
            uint2 r = *(const uint2*)(sp + j);
            float2 f0 = __half22float2(*reinterpret_cast<__half2*>(&r.x));
            float2 f1 = __half22float2(*reinterpret_cast<__half2*>(&r.y));
            wv = make_float4(f0.x * inv, f0.y * inv, f1.x * inv, f1.y * inv);
        } else {
            wv = zf;
        }
        *(float4*)(ap + j) = wv;
    }
}

// ---------------- pass3: masked rows -> uniform mean of V -------------------
__global__ __launch_bounds__(64) void attn_pass3(
    const unsigned char* __restrict__ mask,
    const float* __restrict__ v, float* __restrict__ out)
{
    const int row = blockIdx.x * 64 + threadIdx.x;   // b*L + i
    const bool m = mask[row] != 0;
    if (!__syncthreads_or(m)) return;                // fast path: no masked rows
    if (!m) return;
    const int b = row >> 12;
    const float* vb = v + (size_t)b * LL * DD;
    for (int d = 0; d < DD; d++) {
        float s = 0.f;
        for (int kk = 0; kk < LL; kk++) s += vb[(size_t)kk * DD + d];
        out[(size_t)row * DD + d] = s * (1.0f / (float)LL);
    }
}

extern "C" void kernel_launch(void* const* d_in, const int* in_sizes, int n_in,
                              void* d_out, int out_size)
{
    (void)in_sizes; (void)n_in; (void)out_size;
    const float* q = (const float*)d_in[0];
    const float* k = (const float*)d_in[1];
    const float* v = (const float*)d_in[2];
    const unsigned char* mask = (const unsigned char*)d_in[3];

    float* out = (float*)d_out;
    float* attn = out + (size_t)BB * LL * DD;

    cudaFuncSetAttribute(attn_pass1, cudaFuncAttributeMaxDynamicSharedMemorySize, SMEM_TOTAL);

    const int NCONV = (int)(3 * (size_t)BB * LL * DD / 8 / 256);  // 6144 blocks
    convert_h<<<NCONV, 256>>>(q, k, v);
    attn_pass1<<<dim3(NQT, BB), 256, SMEM_TOTAL>>>(mask, out);
    attn_pass2<<<BB * LL, 256>>>(mask, attn);
    attn_pass3<<<BB * LL / 64, 64>>>(mask, v, out);
}